// round 1
// baseline (speedup 1.0000x reference)
#include <cuda_runtime.h>

#define BB 16
#define TT 1024
#define SS 256
#define CC 256
#define NCONV 8
#define MM 16
#define LN_EPS 1e-3f

#define TTILE 16   // t's per block in k2
#define TG 4       // t-group for register blocking

// ---------------- scratch (device globals; no allocations) ----------------
__device__ float g_part[BB * 8 * SS * 16];  // conv partial sums: [b][chunk][s][path*8+cc]
__device__ float g_cw[BB * SS * 16];        // layer-1 constant vector, w path
__device__ float g_ca[BB * SS * 16];        // layer-1 constant vector, a path

__device__ __forceinline__ float silu_f(float x) {
    float e = __expf(-x);
    return __fdividef(x, 1.0f + e);
}

// ================= K1a: conv partials over 32-channel chunks =================
// grid = B*8 blocks, 256 threads (thread = s)
__global__ __launch_bounds__(256) void k1a_conv(
    const float* __restrict__ ctx,
    const float* __restrict__ wcw,
    const float* __restrict__ wca)
{
    __shared__ float s_ctx[SS * 33];
    __shared__ float s_w[2][3 * 32 * 8];

    int b = blockIdx.x >> 3;
    int chunk = blockIdx.x & 7;
    int c0 = chunk * 32;
    int tid = threadIdx.x;

    for (int i = tid; i < SS * 32; i += 256) {
        int row = i >> 5, c = i & 31;
        s_ctx[row * 33 + c] = ctx[((size_t)b * SS + row) * CC + c0 + c];
    }
    for (int i = tid; i < 3 * 32 * 8; i += 256) {
        int k = i / 256, rem = i % 256;   // rem = c*8+cc over the 32-chunk
        s_w[0][i] = wcw[(size_t)k * CC * 8 + (size_t)c0 * 8 + rem];
        s_w[1][i] = wca[(size_t)k * CC * 8 + (size_t)c0 * 8 + rem];
    }
    __syncthreads();

    int s = tid;
    float hw[8], ha[8];
    #pragma unroll
    for (int cc = 0; cc < 8; cc++) { hw[cc] = 0.f; ha[cc] = 0.f; }

    #pragma unroll
    for (int k = 0; k < 3; k++) {
        int row = s + k - 1;
        if (row < 0 || row >= SS) continue;
        for (int c = 0; c < 32; c++) {
            float v = s_ctx[row * 33 + c];
            #pragma unroll
            for (int cc = 0; cc < 8; cc++) {
                hw[cc] = fmaf(v, s_w[0][(k * 32 + c) * 8 + cc], hw[cc]);
                ha[cc] = fmaf(v, s_w[1][(k * 32 + c) * 8 + cc], ha[cc]);
            }
        }
    }
    float* dst = &g_part[(((size_t)b * 8 + chunk) * SS + s) * 16];
    #pragma unroll
    for (int cc = 0; cc < 8; cc++) { dst[cc] = hw[cc]; dst[8 + cc] = ha[cc]; }
}

// ========== K1b: cumsum + reduce partials + LN + silu + c-vectors ==========
// grid = B blocks, 256 threads (thread = s)
__global__ __launch_bounds__(256) void k1b_setup(
    const float* __restrict__ dur,
    const float* __restrict__ bcw, const float* __restrict__ glnw,
    const float* __restrict__ blnw, const float* __restrict__ w1w,
    const float* __restrict__ b1w,
    const float* __restrict__ bca, const float* __restrict__ glna,
    const float* __restrict__ blna, const float* __restrict__ w1a,
    const float* __restrict__ b1a)
{
    __shared__ float s_scan[SS];
    int b = blockIdx.x, s = threadIdx.x;

    float d = dur[(size_t)b * SS + s];
    s_scan[s] = d;
    __syncthreads();
    for (int off = 1; off < SS; off <<= 1) {
        float v = (s >= off) ? s_scan[s - off] : 0.f;
        __syncthreads();
        s_scan[s] += v;
        __syncthreads();
    }
    float e0 = s_scan[s];
    float s0 = e0 - d;

    float h[16];
    #pragma unroll
    for (int p = 0; p < 16; p++) h[p] = 0.f;
    for (int ch = 0; ch < 8; ch++) {
        const float* src = &g_part[(((size_t)b * 8 + ch) * SS + s) * 16];
        #pragma unroll
        for (int p = 0; p < 16; p++) h[p] += src[p];
    }

    for (int p = 0; p < 2; p++) {
        const float* bconv = (p == 0) ? bcw : bca;
        const float* gln   = (p == 0) ? glnw : glna;
        const float* bln   = (p == 0) ? blnw : blna;
        const float* w1    = (p == 0) ? w1w : w1a;
        const float* b1    = (p == 0) ? b1w : b1a;
        float* dst         = (p == 0) ? g_cw : g_ca;

        float hv[8];
        float mu = 0.f;
        #pragma unroll
        for (int cc = 0; cc < 8; cc++) {
            hv[cc] = h[p * 8 + cc] + bconv[cc];
            mu += hv[cc];
        }
        mu *= 0.125f;
        float var = 0.f;
        #pragma unroll
        for (int cc = 0; cc < 8; cc++) {
            float dd = hv[cc] - mu;
            var += dd * dd;
        }
        var *= 0.125f;
        float inv = rsqrtf(var + LN_EPS);
        float hs[8];
        #pragma unroll
        for (int cc = 0; cc < 8; cc++)
            hs[cc] = silu_f((hv[cc] - mu) * inv * gln[cc] + bln[cc]);

        #pragma unroll
        for (int j = 0; j < 16; j++) {
            float val = b1[j] - s0 * w1[8 * 16 + j] + (e0 + s0) * w1[9 * 16 + j];
            #pragma unroll
            for (int cc = 0; cc < 8; cc++)
                val = fmaf(hs[cc], w1[cc * 16 + j], val);
            dst[((size_t)b * SS + s) * 16 + j] = val;
        }
    }
}

// ======================== block reductions for k2 ========================
__device__ __forceinline__ float warpMax(float v) {
    #pragma unroll
    for (int off = 16; off > 0; off >>= 1)
        v = fmaxf(v, __shfl_xor_sync(0xffffffffu, v, off));
    return v;
}
__device__ __forceinline__ float warpSum(float v) {
    #pragma unroll
    for (int off = 16; off > 0; off >>= 1)
        v += __shfl_xor_sync(0xffffffffu, v, off);
    return v;
}
__device__ __forceinline__ float blockMax(float v, float* s_red, int tid) {
    int lane = tid & 31, wid = tid >> 5;
    v = warpMax(v);
    if (lane == 0) s_red[wid] = v;
    __syncthreads();
    if (wid == 0) {
        float r = (lane < 8) ? s_red[lane] : -3.4e38f;
        r = warpMax(r);
        if (lane == 0) s_red[32] = r;
    }
    __syncthreads();
    return s_red[32];
}
__device__ __forceinline__ float blockSum(float v, float* s_red, int tid) {
    int lane = tid & 31, wid = tid >> 5;
    v = warpSum(v);
    if (lane == 0) s_red[wid] = v;
    __syncthreads();
    if (wid == 0) {
        float r = (lane < 8) ? s_red[lane] : 0.f;
        r = warpSum(r);
        if (lane == 0) s_red[32] = r;
    }
    __syncthreads();
    return s_red[32];
}

// ===================== K2: fused main kernel =====================
// grid = (T/TTILE, B), 256 threads
// dyn smem layout (floats):
//   s_cw    [0,      4352)  256*17   (aliased as s_concat 16*272 later)
//   s_ca    [4352,   8704)  256*17
//   s_wt    [8704,  12800)  16*256
//   s_w2w   [12800, 13056)
//   s_w2a   [13056, 13312)
//   s_small [13312, 13408)  dw16 | da16 | wpw16 | b2w16 | b2a16
//   s_part  [13408, 15456)  16*8*16
//   s_red   [15456, 15496)
#define K2_SMEM_FLOATS 15496
#define K2_SMEM_BYTES (K2_SMEM_FLOATS * 4)

__global__ __launch_bounds__(256, 2) void k2_main(
    const float* __restrict__ ctx, const float* __restrict__ mask,
    const float* __restrict__ w1w, const float* __restrict__ w2w,
    const float* __restrict__ b2w, const float* __restrict__ wpw,
    const float* __restrict__ bpw,
    const float* __restrict__ w1a, const float* __restrict__ w2a,
    const float* __restrict__ b2a,
    const float* __restrict__ wpa, const float* __restrict__ bpa,
    float* __restrict__ out)
{
    extern __shared__ float sm[];
    float* s_cw     = sm;
    float* s_ca     = sm + 4352;
    float* s_wt     = sm + 8704;
    float* s_w2w    = sm + 12800;
    float* s_w2a    = sm + 13056;
    float* s_small  = sm + 13312;
    float* s_part   = sm + 13408;
    float* s_red    = sm + 15456;
    float* s_concat = s_cw;  // alias: s_cw dead after phase 1a

    int tid = threadIdx.x;
    int lane = tid & 31, wid = tid >> 5;
    int b = blockIdx.y;
    int t0 = blockIdx.x * TTILE;

    // ---- load weights ----
    s_w2w[tid] = w2w[tid];
    s_w2a[tid] = w2a[tid];
    if (tid < 16) {
        s_small[tid]      = w1w[128 + tid] - w1w[144 + tid];  // dw
        s_small[16 + tid] = w1a[128 + tid] - w1a[144 + tid];  // da
        s_small[32 + tid] = wpw[tid];
        s_small[48 + tid] = b2w[tid];
        s_small[64 + tid] = b2a[tid];
    }
    {
        const float4* cw4 = (const float4*)&g_cw[((size_t)b * SS + tid) * 16];
        const float4* ca4 = (const float4*)&g_ca[((size_t)b * SS + tid) * 16];
        #pragma unroll
        for (int q = 0; q < 4; q++) {
            float4 v = cw4[q];
            s_cw[tid * 17 + q * 4 + 0] = v.x; s_cw[tid * 17 + q * 4 + 1] = v.y;
            s_cw[tid * 17 + q * 4 + 2] = v.z; s_cw[tid * 17 + q * 4 + 3] = v.w;
            float4 w = ca4[q];
            s_ca[tid * 17 + q * 4 + 0] = w.x; s_ca[tid * 17 + q * 4 + 1] = w.y;
            s_ca[tid * 17 + q * 4 + 2] = w.z; s_ca[tid * 17 + q * 4 + 3] = w.w;
        }
    }
    float bp0 = bpw[0];
    __syncthreads();

    // ---- Phase 1a: logits for all TTILE t's (t-grouped by TG) ----
    for (int g = 0; g < TTILE / TG; g++) {
        float y[TG][16];
        #pragma unroll
        for (int u = 0; u < TG; u++)
            #pragma unroll
            for (int i = 0; i < 16; i++) y[u][i] = s_small[48 + i];

        for (int j = 0; j < 16; j++) {
            float cv = s_cw[tid * 17 + j];
            float dv = s_small[j];
            float xj[TG];
            #pragma unroll
            for (int u = 0; u < TG; u++)
                xj[u] = silu_f(fmaf((float)(t0 + g * TG + u), dv, cv));
            #pragma unroll
            for (int i = 0; i < 16; i++) {
                float w = s_w2w[j * 16 + i];
                #pragma unroll
                for (int u = 0; u < TG; u++)
                    y[u][i] = fmaf(xj[u], w, y[u][i]);
            }
        }
        #pragma unroll
        for (int u = 0; u < TG; u++) {
            float lg = bp0;
            #pragma unroll
            for (int i = 0; i < 16; i++)
                lg = fmaf(silu_f(y[u][i]), s_small[32 + i], lg);
            s_wt[(g * TG + u) * SS + tid] = lg;
        }
    }
    __syncthreads();

    // ---- Phase 1b: masked softmax per t, write w output ----
    float m0  = mask[((size_t)b * TT) * SS + tid];
    float neg = (1.0f - m0) * (-1000000.0f);
    for (int t = 0; t < TTILE; t++) {
        float lg = fmaf(m0, s_wt[t * SS + tid], neg);
        float mx = blockMax(lg, s_red, tid);
        float p  = __expf(lg - mx);
        float sum = blockSum(p, s_red, tid);
        float wv = __fdividef(p, sum) * mask[((size_t)b * TT + (t0 + t)) * SS + tid];
        s_wt[t * SS + tid] = wv;
        out[((size_t)b * TT + (t0 + t)) * SS + tid] = wv;
    }

    // ---- Phase 1c: a-path MLP, weighted + warp-reduced ----
    for (int g = 0; g < TTILE / TG; g++) {
        float y[TG][16];
        #pragma unroll
        for (int u = 0; u < TG; u++)
            #pragma unroll
            for (int i = 0; i < 16; i++) y[u][i] = s_small[64 + i];

        for (int j = 0; j < 16; j++) {
            float cv = s_ca[tid * 17 + j];
            float dv = s_small[16 + j];
            float xj[TG];
            #pragma unroll
            for (int u = 0; u < TG; u++)
                xj[u] = silu_f(fmaf((float)(t0 + g * TG + u), dv, cv));
            #pragma unroll
            for (int i = 0; i < 16; i++) {
                float w = s_w2a[j * 16 + i];
                #pragma unroll
                for (int u = 0; u < TG; u++)
                    y[u][i] = fmaf(xj[u], w, y[u][i]);
            }
        }
        #pragma unroll
        for (int u = 0; u < TG; u++) {
            float wv = s_wt[(g * TG + u) * SS + tid];
            #pragma unroll
            for (int i = 0; i < 16; i++)
                y[u][i] = silu_f(y[u][i]) * wv;
        }
        #pragma unroll
        for (int off = 16; off > 0; off >>= 1)
            #pragma unroll
            for (int u = 0; u < TG; u++)
                #pragma unroll
                for (int i = 0; i < 16; i++)
                    y[u][i] += __shfl_xor_sync(0xffffffffu, y[u][i], off);
        if (lane == 0) {
            #pragma unroll
            for (int u = 0; u < TG; u++)
                #pragma unroll
                for (int i = 0; i < 16; i++)
                    s_part[((g * TG + u) * 8 + wid) * 16 + i] = y[u][i];
        }
    }
    __syncthreads();

    // ---- Phase 1d: finish aux reduction -> s_concat[t][256+m] ----
    {
        int t = tid >> 4, m = tid & 15;
        float a = 0.f;
        #pragma unroll
        for (int w8 = 0; w8 < 8; w8++)
            a += s_part[(t * 8 + w8) * 16 + m];
        s_concat[t * 272 + 256 + m] = a;
    }

    // ---- Phase 2: aligned = w @ context -> s_concat[t][0..255] ----
    int cg = (tid & 63) * 4;
    int tg = (tid >> 6) * 4;
    {
        float acc[4][4];
        #pragma unroll
        for (int u = 0; u < 4; u++)
            #pragma unroll
            for (int q = 0; q < 4; q++) acc[u][q] = 0.f;
        const float4* ctx4 = (const float4*)(ctx + (size_t)b * SS * CC);
        for (int s = 0; s < SS; s++) {
            float4 v = ctx4[s * 64 + (tid & 63)];
            #pragma unroll
            for (int u = 0; u < 4; u++) {
                float wv = s_wt[(tg + u) * SS + s];
                acc[u][0] = fmaf(wv, v.x, acc[u][0]);
                acc[u][1] = fmaf(wv, v.y, acc[u][1]);
                acc[u][2] = fmaf(wv, v.z, acc[u][2]);
                acc[u][3] = fmaf(wv, v.w, acc[u][3]);
            }
        }
        #pragma unroll
        for (int u = 0; u < 4; u++)
            #pragma unroll
            for (int q = 0; q < 4; q++)
                s_concat[(tg + u) * 272 + cg + q] = acc[u][q];
    }
    __syncthreads();

    // ---- Phase 3: out_aligned = concat @ w_pa + b_pa ----
    {
        float acc2[4][4];
        float4 bp = ((const float4*)bpa)[tid & 63];
        #pragma unroll
        for (int u = 0; u < 4; u++) {
            acc2[u][0] = bp.x; acc2[u][1] = bp.y;
            acc2[u][2] = bp.z; acc2[u][3] = bp.w;
        }
        const float4* wpa4 = (const float4*)wpa;
        for (int k = 0; k < 272; k++) {
            float4 wv = wpa4[k * 64 + (tid & 63)];
            #pragma unroll
            for (int u = 0; u < 4; u++) {
                float xv = s_concat[(tg + u) * 272 + k];
                acc2[u][0] = fmaf(xv, wv.x, acc2[u][0]);
                acc2[u][1] = fmaf(xv, wv.y, acc2[u][1]);
                acc2[u][2] = fmaf(xv, wv.z, acc2[u][2]);
                acc2[u][3] = fmaf(xv, wv.w, acc2[u][3]);
            }
        }
        float* oal = out + (size_t)BB * TT * SS;
        #pragma unroll
        for (int u = 0; u < 4; u++) {
            float4 o = make_float4(acc2[u][0], acc2[u][1], acc2[u][2], acc2[u][3]);
            ((float4*)oal)[(((size_t)b * TT + (t0 + tg + u)) * CC + cg) >> 2] = o;
        }
    }
}

// ============================ launch ============================
extern "C" void kernel_launch(void* const* d_in, const int* in_sizes, int n_in,
                              void* d_out, int out_size) {
    (void)in_sizes; (void)n_in; (void)out_size;
    const float* ctx  = (const float*)d_in[0];
    const float* dur  = (const float*)d_in[1];
    const float* mask = (const float*)d_in[2];
    const float* wcw  = (const float*)d_in[3];
    const float* bcw  = (const float*)d_in[4];
    const float* glnw = (const float*)d_in[5];
    const float* blnw = (const float*)d_in[6];
    const float* w1w  = (const float*)d_in[7];
    const float* b1w  = (const float*)d_in[8];
    const float* w2w  = (const float*)d_in[9];
    const float* b2w  = (const float*)d_in[10];
    const float* wpw  = (const float*)d_in[11];
    const float* bpw  = (const float*)d_in[12];
    const float* wca  = (const float*)d_in[13];
    const float* bca  = (const float*)d_in[14];
    const float* glna = (const float*)d_in[15];
    const float* blna = (const float*)d_in[16];
    const float* w1a  = (const float*)d_in[17];
    const float* b1a  = (const float*)d_in[18];
    const float* w2a  = (const float*)d_in[19];
    const float* b2a  = (const float*)d_in[20];
    const float* wpa  = (const float*)d_in[21];
    const float* bpa  = (const float*)d_in[22];
    float* out = (float*)d_out;

    k1a_conv<<<BB * 8, 256>>>(ctx, wcw, wca);
    k1b_setup<<<BB, 256>>>(dur, bcw, glnw, blnw, w1w, b1w,
                           bca, glna, blna, w1a, b1a);

    cudaFuncSetAttribute(k2_main, cudaFuncAttributeMaxDynamicSharedMemorySize,
                         K2_SMEM_BYTES);
    dim3 grid(TT / TTILE, BB);
    k2_main<<<grid, 256, K2_SMEM_BYTES>>>(
        ctx, mask, w1w, w2w, b2w, wpw, bpw,
        w1a, w2a, b2a, wpa, bpa, out);
}